// round 4
// baseline (speedup 1.0000x reference)
#include <cuda_runtime.h>
#include <cuda_bf16.h>

// ---------------------------------------------------------------------------
// NonLocalBlock: B=8, C=256, Ci=128, H=W=64, N=4096, M=1024
// theta = conv1x1(x,theta_w,theta_b)                      (B,128,4096)
// phi   = maxpool2(conv1x1(x,phi_w,phi_b))                (B,128,1024)
// g     = maxpool2(conv1x1(x,g_w,g_b))                    (B,128,1024)
// attn  = softmax_m(theta^T phi)                          (B,4096,1024)
// y     = attn @ g^T  -> (B,128,4096)
// z     = conv1x1(y, W_w, W_b); BN(train stats); out = x + BN(z)
// ---------------------------------------------------------------------------

#define NB 8
#define CC 256
#define CI 128
#define NN 4096
#define MM 1024

typedef unsigned long long u64;

__device__ __forceinline__ u64 pack2(float lo, float hi) {
    u64 r; asm("mov.b64 %0, {%1, %2};" : "=l"(r) : "f"(lo), "f"(hi)); return r;
}
__device__ __forceinline__ void fma2(u64& d, u64 a, u64 b) {
    asm("fma.rn.f32x2 %0, %1, %2, %0;" : "+l"(d) : "l"(a), "l"(b));
}
__device__ __forceinline__ float2 unpack2(u64 v) {
    float2 f; asm("mov.b64 {%0, %1}, %2;" : "=f"(f.x), "=f"(f.y) : "l"(v)); return f;
}

// exp(x) for x <= 0 without MUFU: 2^(x*log2e) via exponent splice + deg-7 poly.
__device__ __forceinline__ float fast_exp(float x) {
    float y = x * 1.44269504088896340736f;
    y = fmaxf(y, -126.0f);
    float k = floorf(y);
    float f = y - k;                      // [0,1)
    const float c1 = 0.6931471805599453f, c2 = 0.2402265069591007f,
                c3 = 0.05550410866482158f, c4 = 0.009618129107628477f,
                c5 = 0.0013333558146428443f, c6 = 1.540353039338161e-4f,
                c7 = 1.52527338040598e-5f;
    float p = fmaf(c7, f, c6);
    p = fmaf(p, f, c5); p = fmaf(p, f, c4); p = fmaf(p, f, c3);
    p = fmaf(p, f, c2); p = fmaf(p, f, c1); p = fmaf(p, f, 1.0f);
    int ik = (int)k;
    float s = __int_as_float((ik + 127) << 23);
    return p * s;
}

// ----------------------------- scratch ------------------------------------
__device__ float g_theta[NB * CI * NN];   // 16 MB
__device__ float g_phif [NB * CI * NN];   // 16 MB (pre-pool phi)
__device__ float g_gf   [NB * CI * NN];   // 16 MB (pre-pool g)
__device__ float g_phip [NB * CI * MM];   // 4 MB
__device__ float g_gp   [NB * CI * MM];   // 4 MB
__device__ float g_y    [NB * CI * NN];   // 16 MB (attention output)
__device__ float g_z    [NB * CC * NN];   // 32 MB (W projection)
__device__ float g_psum [CC * 512];       // deterministic BN partials
__device__ float g_psumsq[CC * 512];
__device__ float g_bna[CC], g_bnb[CC];

// ---------------------------------------------------------------------------
// K1: three projection GEMMs: out[o,n] = sum_c w[o,c]*x[b,c,n] + bias[o]
// grid (64 n-tiles, 6 o-tiles(=384/64), 8 batches), 256 threads, 64x64 tile.
// ---------------------------------------------------------------------------
__global__ __launch_bounds__(256) void proj_kernel(
    const float* __restrict__ x,
    const float* __restrict__ tw, const float* __restrict__ tb,
    const float* __restrict__ pw, const float* __restrict__ pb,
    const float* __restrict__ gw, const float* __restrict__ gb)
{
    __shared__ float ws[16][64];   // [k][o]
    __shared__ float xs[16][64];   // [k][n]
    int b = blockIdx.z, ot = blockIdx.y, n0 = blockIdx.x * 64;
    const float *w, *bias; float* outb; int o0;
    if (ot < 2)      { w = tw; bias = tb; outb = g_theta; o0 = ot * 64; }
    else if (ot < 4) { w = pw; bias = pb; outb = g_phif;  o0 = (ot - 2) * 64; }
    else             { w = gw; bias = gb; outb = g_gf;    o0 = (ot - 4) * 64; }
    const float* xb = x + b * CC * NN;
    float* ob = outb + b * CI * NN;
    int tid = threadIdx.x, ty = tid >> 4, tx = tid & 15;
    int rr = tid >> 2, ss = tid & 3;
    u64 acc[4][2] = {};

    for (int k0 = 0; k0 < CC; k0 += 16) {
        __syncthreads();
        float4 wv = *(const float4*)&w[(o0 + rr) * CC + k0 + ss * 4];
        ws[ss * 4 + 0][rr] = wv.x; ws[ss * 4 + 1][rr] = wv.y;
        ws[ss * 4 + 2][rr] = wv.z; ws[ss * 4 + 3][rr] = wv.w;
        *(float4*)&xs[ty][tx * 4] = *(const float4*)&xb[(k0 + ty) * NN + n0 + tx * 4];
        __syncthreads();
#pragma unroll
        for (int k = 0; k < 16; k++) {
            float4 av = *(float4*)&ws[k][ty * 4];
            float4 bv = *(float4*)&xs[k][tx * 4];
            u64 b01 = pack2(bv.x, bv.y), b23 = pack2(bv.z, bv.w);
            u64 d;
            d = pack2(av.x, av.x); fma2(acc[0][0], d, b01); fma2(acc[0][1], d, b23);
            d = pack2(av.y, av.y); fma2(acc[1][0], d, b01); fma2(acc[1][1], d, b23);
            d = pack2(av.z, av.z); fma2(acc[2][0], d, b01); fma2(acc[2][1], d, b23);
            d = pack2(av.w, av.w); fma2(acc[3][0], d, b01); fma2(acc[3][1], d, b23);
        }
    }
#pragma unroll
    for (int oi = 0; oi < 4; oi++) {
        int o = o0 + ty * 4 + oi;
        float bv = bias[o];
        float2 p0 = unpack2(acc[oi][0]), p1 = unpack2(acc[oi][1]);
        *(float4*)&ob[o * NN + n0 + tx * 4] =
            make_float4(p0.x + bv, p0.y + bv, p1.x + bv, p1.y + bv);
    }
}

// ---------------------------------------------------------------------------
// K1b: 2x2 max-pool for phi and g (pre-pool -> pooled). 2 outputs/thread.
// ---------------------------------------------------------------------------
__global__ __launch_bounds__(256) void pool_kernel()
{
    int gid = blockIdx.x * 256 + threadIdx.x;            // 0 .. 2*524288-1
    const float* src; float* dst; int rid;
    if (gid < 524288) { src = g_phif; dst = g_phip; rid = gid; }
    else              { src = g_gf;   dst = g_gp;   rid = gid - 524288; }
    int wp = rid & 15, hp = (rid >> 4) & 31, bc = rid >> 9;  // bc in [0,1024)
    const float* in = src + bc * 4096 + hp * 128 + wp * 4;
    float4 a = *(const float4*)in;
    float4 c = *(const float4*)(in + 64);
    float2 o;
    o.x = fmaxf(fmaxf(a.x, a.y), fmaxf(c.x, c.y));
    o.y = fmaxf(fmaxf(a.z, a.w), fmaxf(c.z, c.w));
    *(float2*)(dst + bc * 1024 + hp * 32 + wp * 2) = o;
}

// ---------------------------------------------------------------------------
// K2: fused attention. One CTA = (batch, 32 n-rows). Full M=1024 score tile
// in smem, stored [m][n]-major. Phase1: S = Th^T * Phi. Phase2: softmax over
// m (unnormalized exp kept, 1/sum folded into epilogue). Phase3: Y = P * G^T.
// ---------------------------------------------------------------------------
#define SMEM_FLOATS (4096 + 32768 + 16896 + 256 + 256 + 32)
#define SMEM_BYTES  (SMEM_FLOATS * 4)

__global__ __launch_bounds__(256) void attn_kernel()
{
    extern __shared__ float sm[];
    float* Th     = sm;               // [128][32]
    float* St     = sm + 4096;        // [1024][32]
    float* Ck     = St + 32768;       // [128][132]  phi / g chunk
    float* red1   = Ck + 16896;       // [8][32]
    float* red2   = red1 + 256;       // [8][32]
    float* rowinv = red2 + 256;       // [32]

    int b = blockIdx.y, n0 = blockIdx.x * 32;
    int tid = threadIdx.x;
    const float* thb = g_theta + b * (CI * NN);
    const float* phb = g_phip  + b * (CI * MM);
    const float* gpb = g_gp    + b * (CI * MM);

#pragma unroll
    for (int t = 0; t < 4; t++) {
        int id = tid + t * 256;
        int ci = id >> 3, s = id & 7;
        *(float4*)&Th[ci * 32 + s * 4] = *(const float4*)&thb[ci * NN + n0 + s * 4];
    }

    int tn = tid & 7, tm = tid >> 3;
    int nl = tn * 4, ml = tm * 4;

    // ---- phase 1: scores -------------------------------------------------
    for (int mc = 0; mc < 8; mc++) {
        __syncthreads();
#pragma unroll
        for (int t = 0; t < 16; t++) {           // 4096 float4s = 128ci x 128m
            int id = tid + t * 256;
            int ci = id >> 5, s = id & 31;
            *(float4*)&Ck[ci * 132 + s * 4] =
                *(const float4*)&phb[ci * MM + mc * 128 + s * 4];
        }
        __syncthreads();
        u64 acc[4][2] = {};
#pragma unroll 4
        for (int ci = 0; ci < CI; ci++) {
            float4 a = *(float4*)&Th[ci * 32 + nl];
            float4 p = *(float4*)&Ck[ci * 132 + ml];
            u64 a01 = pack2(a.x, a.y), a23 = pack2(a.z, a.w);
            u64 d;
            d = pack2(p.x, p.x); fma2(acc[0][0], a01, d); fma2(acc[0][1], a23, d);
            d = pack2(p.y, p.y); fma2(acc[1][0], a01, d); fma2(acc[1][1], a23, d);
            d = pack2(p.z, p.z); fma2(acc[2][0], a01, d); fma2(acc[2][1], a23, d);
            d = pack2(p.w, p.w); fma2(acc[3][0], a01, d); fma2(acc[3][1], a23, d);
        }
#pragma unroll
        for (int mi = 0; mi < 4; mi++) {
            float2 q0 = unpack2(acc[mi][0]), q1 = unpack2(acc[mi][1]);
            *(float4*)&St[(mc * 128 + ml + mi) * 32 + nl] =
                make_float4(q0.x, q0.y, q1.x, q1.y);
        }
    }
    __syncthreads();

    // ---- phase 2: softmax (per column n), unnormalized exp ---------------
    {
        int w = tid >> 5, l = tid & 31;
        float mx = -3.0e38f;
        for (int m = w * 128; m < (w + 1) * 128; m++)
            mx = fmaxf(mx, St[m * 32 + l]);
        red1[w * 32 + l] = mx;
        __syncthreads();
        float gmx = red1[l];
#pragma unroll
        for (int i = 1; i < 8; i++) gmx = fmaxf(gmx, red1[i * 32 + l]);
        float s = 0.f;
        for (int m = w * 128; m < (w + 1) * 128; m++) {
            float v = fast_exp(St[m * 32 + l] - gmx);
            St[m * 32 + l] = v;
            s += v;
        }
        red2[w * 32 + l] = s;
        __syncthreads();
        if (w == 0) {
            float t = red2[l];
#pragma unroll
            for (int i = 1; i < 8; i++) t += red2[i * 32 + l];
            rowinv[l] = 1.0f / t;
        }
    }

    // ---- phase 3: Y = P * G^T --------------------------------------------
    int tn3 = tid & 3, tc3 = tid >> 2;   // 8 n's, 2 ci's per thread
    u64 acc3[2][4] = {};
    for (int mc = 0; mc < 8; mc++) {
        __syncthreads();
#pragma unroll
        for (int t = 0; t < 16; t++) {           // 4096 float4s = 128ci x 128m
            int id = tid + t * 256;
            int ci = id >> 5, s = id & 31;
            *(float4*)&Ck[ci * 132 + s * 4] =
                *(const float4*)&gpb[ci * MM + mc * 128 + s * 4];
        }
        __syncthreads();
        const float* g0p = &Ck[(tc3 * 2) * 132];
        const float* g1p = &Ck[(tc3 * 2 + 1) * 132];
        int sb = (mc * 128) * 32 + tn3 * 8;
#pragma unroll 4
        for (int m = 0; m < 128; m++) {
            float4 p0 = *(float4*)&St[sb + m * 32];
            float4 p1 = *(float4*)&St[sb + m * 32 + 4];
            float gg0 = g0p[m], gg1 = g1p[m];
            u64 d0 = pack2(gg0, gg0), d1 = pack2(gg1, gg1);
            u64 pp;
            pp = pack2(p0.x, p0.y); fma2(acc3[0][0], pp, d0); fma2(acc3[1][0], pp, d1);
            pp = pack2(p0.z, p0.w); fma2(acc3[0][1], pp, d0); fma2(acc3[1][1], pp, d1);
            pp = pack2(p1.x, p1.y); fma2(acc3[0][2], pp, d0); fma2(acc3[1][2], pp, d1);
            pp = pack2(p1.z, p1.w); fma2(acc3[0][3], pp, d0); fma2(acc3[1][3], pp, d1);
        }
    }

    float* yb = g_y + b * (CI * NN);
    float inv[8];
#pragma unroll
    for (int j = 0; j < 8; j++) inv[j] = rowinv[tn3 * 8 + j];
#pragma unroll
    for (int q = 0; q < 2; q++) {
        int ci = tc3 * 2 + q;
        float2 r0 = unpack2(acc3[q][0]), r1 = unpack2(acc3[q][1]);
        float2 r2 = unpack2(acc3[q][2]), r3 = unpack2(acc3[q][3]);
        *(float4*)&yb[ci * NN + n0 + tn3 * 8] =
            make_float4(r0.x * inv[0], r0.y * inv[1], r1.x * inv[2], r1.y * inv[3]);
        *(float4*)&yb[ci * NN + n0 + tn3 * 8 + 4] =
            make_float4(r2.x * inv[4], r2.y * inv[5], r3.x * inv[6], r3.y * inv[7]);
    }
}

// ---------------------------------------------------------------------------
// K3: output projection GEMM z = W_w @ y + W_b, with deterministic per-CTA
// BN partial sums (sum, sumsq per channel) written to g_psum/g_psumsq.
// ---------------------------------------------------------------------------
__global__ __launch_bounds__(256) void wproj_kernel(
    const float* __restrict__ w, const float* __restrict__ bias)
{
    __shared__ float ws[16][64];
    __shared__ float xs[16][64];
    int b = blockIdx.z, o0 = blockIdx.y * 64, n0 = blockIdx.x * 64;
    const float* xb = g_y + b * CI * NN;
    float* ob = g_z + b * CC * NN;
    int tid = threadIdx.x, ty = tid >> 4, tx = tid & 15;
    int rr = tid >> 2, ss = tid & 3;
    u64 acc[4][2] = {};

    for (int k0 = 0; k0 < CI; k0 += 16) {
        __syncthreads();
        float4 wv = *(const float4*)&w[(o0 + rr) * CI + k0 + ss * 4];
        ws[ss * 4 + 0][rr] = wv.x; ws[ss * 4 + 1][rr] = wv.y;
        ws[ss * 4 + 2][rr] = wv.z; ws[ss * 4 + 3][rr] = wv.w;
        *(float4*)&xs[ty][tx * 4] = *(const float4*)&xb[(k0 + ty) * NN + n0 + tx * 4];
        __syncthreads();
#pragma unroll
        for (int k = 0; k < 16; k++) {
            float4 av = *(float4*)&ws[k][ty * 4];
            float4 bv = *(float4*)&xs[k][tx * 4];
            u64 b01 = pack2(bv.x, bv.y), b23 = pack2(bv.z, bv.w);
            u64 d;
            d = pack2(av.x, av.x); fma2(acc[0][0], d, b01); fma2(acc[0][1], d, b23);
            d = pack2(av.y, av.y); fma2(acc[1][0], d, b01); fma2(acc[1][1], d, b23);
            d = pack2(av.z, av.z); fma2(acc[2][0], d, b01); fma2(acc[2][1], d, b23);
            d = pack2(av.w, av.w); fma2(acc[3][0], d, b01); fma2(acc[3][1], d, b23);
        }
    }
#pragma unroll
    for (int oi = 0; oi < 4; oi++) {
        int o = o0 + ty * 4 + oi;
        float bv = bias[o];
        float2 p0 = unpack2(acc[oi][0]), p1 = unpack2(acc[oi][1]);
        float v0 = p0.x + bv, v1 = p0.y + bv, v2 = p1.x + bv, v3 = p1.y + bv;
        *(float4*)&ob[o * NN + n0 + tx * 4] = make_float4(v0, v1, v2, v3);
        float s  = v0 + v1 + v2 + v3;
        float s2 = v0 * v0 + v1 * v1 + v2 * v2 + v3 * v3;
#pragma unroll
        for (int off = 8; off > 0; off >>= 1) {
            s  += __shfl_xor_sync(0xffffffffu, s,  off);
            s2 += __shfl_xor_sync(0xffffffffu, s2, off);
        }
        if (tx == 0) {
            int slot = b * 64 + blockIdx.x;           // [0,512)
            g_psum  [o * 512 + slot] = s;
            g_psumsq[o * 512 + slot] = s2;
        }
    }
}

// ---------------------------------------------------------------------------
// K4: finalize BN coefficients (deterministic sequential reduce of partials)
// ---------------------------------------------------------------------------
__global__ void bnfin_kernel(const float* __restrict__ gamma,
                             const float* __restrict__ beta)
{
    int c = threadIdx.x;   // 256 threads
    float s = 0.f, s2 = 0.f;
    for (int j = 0; j < 512; j++) { s += g_psum[c * 512 + j]; s2 += g_psumsq[c * 512 + j]; }
    const float inv_n = 1.0f / 32768.0f;
    float mean = s * inv_n;
    float var  = s2 * inv_n - mean * mean;
    float inv  = rsqrtf(var + 1e-5f);
    float a = gamma[c] * inv;
    g_bna[c] = a;
    g_bnb[c] = beta[c] - mean * a;
}

// ---------------------------------------------------------------------------
// K5: out = x + z * a[c] + b[c]
// ---------------------------------------------------------------------------
__global__ __launch_bounds__(256) void final_kernel(
    const float* __restrict__ x, float* __restrict__ out)
{
    int idx = blockIdx.x * 256 + threadIdx.x;   // over 2,097,152 float4s
    int e = idx << 2;
    int c = (e >> 12) & 255;
    float4 xv = *(const float4*)(x + e);
    float4 zv = *((const float4*)g_z + idx);
    float a = g_bna[c], bb = g_bnb[c];
    float4 o;
    o.x = fmaf(zv.x, a, bb) + xv.x;
    o.y = fmaf(zv.y, a, bb) + xv.y;
    o.z = fmaf(zv.z, a, bb) + xv.z;
    o.w = fmaf(zv.w, a, bb) + xv.w;
    *(float4*)(out + e) = o;
}

// ---------------------------------------------------------------------------
extern "C" void kernel_launch(void* const* d_in, const int* in_sizes, int n_in,
                              void* d_out, int out_size)
{
    const float* x     = (const float*)d_in[0];
    const float* tb    = (const float*)d_in[2];
    const float* tw    = (const float*)d_in[1];
    const float* pw    = (const float*)d_in[3];
    const float* pb    = (const float*)d_in[4];
    const float* gw    = (const float*)d_in[5];
    const float* gbv   = (const float*)d_in[6];
    const float* Ww    = (const float*)d_in[7];
    const float* Wb    = (const float*)d_in[8];
    const float* gamma = (const float*)d_in[9];
    const float* beta  = (const float*)d_in[10];
    float* out = (float*)d_out;

    cudaFuncSetAttribute(attn_kernel,
                         cudaFuncAttributeMaxDynamicSharedMemorySize, SMEM_BYTES);

    proj_kernel<<<dim3(64, 6, 8), 256>>>(x, tw, tb, pw, pb, gw, gbv);
    pool_kernel<<<4096, 256>>>();
    attn_kernel<<<dim3(128, 8), 256, SMEM_BYTES>>>();
    wproj_kernel<<<dim3(64, 4, 8), 256>>>(Ww, Wb);
    bnfin_kernel<<<1, 256>>>(gamma, beta);
    final_kernel<<<8192, 256>>>(x, out);
}